// round 5
// baseline (speedup 1.0000x reference)
#include <cuda_runtime.h>
#include <math.h>

// GPT-2 124M forward, fp32 baseline.
// Model constants
#define TT   1024
#define DD   768
#define NH   12
#define HDIM 64
#define NB   4
#define MR   (NB*TT)      // 4096 rows
#define VV   50257
#define NL   12

// ---------------------------------------------------------------------------
// Scratch (static device globals: no allocations allowed)
// ---------------------------------------------------------------------------
__device__ float g_x  [MR * DD];        // residual stream
__device__ float g_h  [MR * DD];        // layernorm output
__device__ float g_qkv[MR * 3 * DD];    // qkv
__device__ float g_att[MR * DD];        // attention output
__device__ float g_fc [MR * 4 * DD];    // mlp hidden

// ---------------------------------------------------------------------------
// Embedding: x = wte[ids] + wpe[t]
// ---------------------------------------------------------------------------
__global__ void embed_kernel(const int* __restrict__ ids,
                             const float* __restrict__ wte,
                             const float* __restrict__ wpe,
                             float* __restrict__ x)
{
    int r = blockIdx.x;            // 0..4095
    int tid = threadIdx.x;         // 0..191 (192 float4 per row)
    int id = ids[r];
    int t  = r & (TT - 1);
    float4 a = *(const float4*)(wte + (size_t)id * DD + tid * 4);
    float4 p = *(const float4*)(wpe + (size_t)t  * DD + tid * 4);
    float4 o;
    o.x = a.x + p.x; o.y = a.y + p.y; o.z = a.z + p.z; o.w = a.w + p.w;
    *(float4*)(x + (size_t)r * DD + tid * 4) = o;
}

// ---------------------------------------------------------------------------
// LayerNorm: one block (256 threads) per row of 768
// ---------------------------------------------------------------------------
__global__ __launch_bounds__(256)
void ln_kernel(const float* __restrict__ in, float* __restrict__ out,
               const float* __restrict__ gamma, const float* __restrict__ beta)
{
    __shared__ float red[8];
    __shared__ float bc;
    int r = blockIdx.x, tid = threadIdx.x;
    const float* row = in + (size_t)r * DD;
    float v0 = row[tid], v1 = row[tid + 256], v2 = row[tid + 512];

    float s = v0 + v1 + v2;
    int lane = tid & 31, wid = tid >> 5;
    #pragma unroll
    for (int o = 16; o > 0; o >>= 1) s += __shfl_xor_sync(0xffffffffu, s, o);
    if (lane == 0) red[wid] = s;
    __syncthreads();
    if (tid == 0) { float t = 0.f; for (int i = 0; i < 8; i++) t += red[i]; bc = t; }
    __syncthreads();
    float mu = bc * (1.0f / 768.0f);

    float d0 = v0 - mu, d1 = v1 - mu, d2 = v2 - mu;
    float sq = d0 * d0 + d1 * d1 + d2 * d2;
    #pragma unroll
    for (int o = 16; o > 0; o >>= 1) sq += __shfl_xor_sync(0xffffffffu, sq, o);
    __syncthreads();
    if (lane == 0) red[wid] = sq;
    __syncthreads();
    if (tid == 0) { float t = 0.f; for (int i = 0; i < 8; i++) t += red[i]; bc = t; }
    __syncthreads();
    float rstd = rsqrtf(bc * (1.0f / 768.0f) + 1e-5f);

    float* orow = out + (size_t)r * DD;
    orow[tid]       = d0 * rstd * gamma[tid]       + beta[tid];
    orow[tid + 256] = d1 * rstd * gamma[tid + 256] + beta[tid + 256];
    orow[tid + 512] = d2 * rstd * gamma[tid + 512] + beta[tid + 512];
}

// ---------------------------------------------------------------------------
// GEMM: C = epilogue(A[M,K] @ B[K,N] (+ bias) (+ residual) (gelu))
// TRANSB: B given as [N,K] row-major (logits: wte^T)
// BM=BN=128, BK=16, 256 threads, 8x8 per thread, double-buffered smem.
// ---------------------------------------------------------------------------
#define EPI_NONE      0
#define EPI_BIAS      1
#define EPI_BIAS_GELU 2
#define EPI_BIAS_RES  3

__device__ __forceinline__ float gelu_f(float x)
{
    const float c = 0.7978845608028654f;
    float inner = c * (x + 0.044715f * x * x * x);
    return 0.5f * x * (1.0f + tanhf(inner));
}

template<int EPI, bool TRANSB>
__global__ __launch_bounds__(256)
void sgemm_kernel(const float* __restrict__ A, const float* __restrict__ Bm,
                  const float* __restrict__ bias, const float* __restrict__ res,
                  float* __restrict__ C, int M, int N, int K)
{
    const int BM = 128, BN = 128, BK = 16;
    __shared__ float As[2][BK][BM];
    __shared__ float Bs[2][BK][BN];

    int tid = threadIdx.x;
    int m0 = blockIdx.x * BM, n0 = blockIdx.y * BN;
    int tx = tid & 15, ty = tid >> 4;

    float acc[8][8];
    #pragma unroll
    for (int i = 0; i < 8; i++)
        #pragma unroll
        for (int j = 0; j < 8; j++) acc[i][j] = 0.0f;

    auto fetch = [&](int k0, float4 (&ra)[2], float4 (&rb)[2]) {
        #pragma unroll
        for (int s = 0; s < 2; s++) {
            int lin = tid + s * 256;
            {
                int row = lin >> 2, c4 = lin & 3;
                ra[s] = *(const float4*)(A + (size_t)(m0 + row) * K + k0 + c4 * 4);
            }
            if (!TRANSB) {
                int kk = lin >> 5, n4 = lin & 31;
                rb[s] = *(const float4*)(Bm + (size_t)(k0 + kk) * N + n0 + n4 * 4);
            } else {
                int nn = lin >> 2, c4 = lin & 3;
                if (n0 + nn < N)
                    rb[s] = *(const float4*)(Bm + (size_t)(n0 + nn) * K + k0 + c4 * 4);
                else
                    rb[s] = make_float4(0.f, 0.f, 0.f, 0.f);
            }
        }
    };
    auto store = [&](int buf, const float4 (&ra)[2], const float4 (&rb)[2]) {
        #pragma unroll
        for (int s = 0; s < 2; s++) {
            int lin = tid + s * 256;
            int row = lin >> 2, c4 = lin & 3;
            As[buf][c4 * 4 + 0][row] = ra[s].x;
            As[buf][c4 * 4 + 1][row] = ra[s].y;
            As[buf][c4 * 4 + 2][row] = ra[s].z;
            As[buf][c4 * 4 + 3][row] = ra[s].w;
            if (!TRANSB) {
                int kk = lin >> 5, n4 = lin & 31;
                *(float4*)&Bs[buf][kk][n4 * 4] = rb[s];
            } else {
                int nn = lin >> 2;
                Bs[buf][c4 * 4 + 0][nn] = rb[s].x;
                Bs[buf][c4 * 4 + 1][nn] = rb[s].y;
                Bs[buf][c4 * 4 + 2][nn] = rb[s].z;
                Bs[buf][c4 * 4 + 3][nn] = rb[s].w;
            }
        }
    };

    float4 ra[2], rb[2];
    fetch(0, ra, rb);
    store(0, ra, rb);
    __syncthreads();

    int nt = K / BK;
    for (int t = 0; t < nt; t++) {
        int cur = t & 1;
        bool has = (t + 1) < nt;
        if (has) fetch((t + 1) * BK, ra, rb);

        #pragma unroll
        for (int k = 0; k < BK; k++) {
            float a[8], b[8];
            *(float4*)&a[0] = *(const float4*)&As[cur][k][ty * 8];
            *(float4*)&a[4] = *(const float4*)&As[cur][k][ty * 8 + 4];
            *(float4*)&b[0] = *(const float4*)&Bs[cur][k][tx * 8];
            *(float4*)&b[4] = *(const float4*)&Bs[cur][k][tx * 8 + 4];
            #pragma unroll
            for (int i = 0; i < 8; i++)
                #pragma unroll
                for (int j = 0; j < 8; j++)
                    acc[i][j] += a[i] * b[j];
        }

        if (has) store(cur ^ 1, ra, rb);
        __syncthreads();
    }

    // epilogue
    #pragma unroll
    for (int i = 0; i < 8; i++) {
        int gm = m0 + ty * 8 + i;
        float* crow = C + (size_t)gm * N;
        const float* rrow = (EPI == EPI_BIAS_RES) ? (res + (size_t)gm * N) : nullptr;
        #pragma unroll
        for (int j = 0; j < 8; j++) {
            int gn = n0 + tx * 8 + j;
            if (TRANSB && gn >= N) continue;
            float v = acc[i][j];
            if (EPI == EPI_BIAS || EPI == EPI_BIAS_GELU || EPI == EPI_BIAS_RES)
                v += bias[gn];
            if (EPI == EPI_BIAS_GELU) v = gelu_f(v);
            if (EPI == EPI_BIAS_RES)  v += rrow[gn];
            crow[gn] = v;
        }
    }
}

// ---------------------------------------------------------------------------
// Attention: one block per (q-tile of 64, head, batch). 64 threads; each
// thread owns one q row (q and o in registers), K/V tiles staged in smem,
// online softmax, causal.
// ---------------------------------------------------------------------------
__global__ __launch_bounds__(64)
void attn_kernel(const float* __restrict__ qkv, float* __restrict__ outp)
{
    __shared__ float Ks[64][64];
    __shared__ float Vs[64][64];
    __shared__ float Ss[64][64];   // Ss[j][t]: per-thread score column (bank-clean)

    int qt = blockIdx.x, h = blockIdx.y, b = blockIdx.z;
    int t = threadIdx.x;
    int qrow = qt * 64 + t;
    const float scale = 0.125f;    // 1/sqrt(64)

    const float* qp = qkv + ((size_t)(b * TT + qrow)) * (3 * DD) + h * HDIM;
    float q[64];
    #pragma unroll
    for (int d4 = 0; d4 < 16; d4++) {
        float4 v = *(const float4*)(qp + d4 * 4);
        q[d4 * 4 + 0] = v.x * scale;
        q[d4 * 4 + 1] = v.y * scale;
        q[d4 * 4 + 2] = v.z * scale;
        q[d4 * 4 + 3] = v.w * scale;
    }
    float o[64];
    #pragma unroll
    for (int d = 0; d < 64; d++) o[d] = 0.0f;
    float m = -3.0e38f, l = 0.0f;

    for (int kt = 0; kt <= qt; kt++) {
        const float* kp = qkv + ((size_t)(b * TT + kt * 64 + t)) * (3 * DD) + DD + h * HDIM;
        #pragma unroll
        for (int d4 = 0; d4 < 16; d4++) {
            *(float4*)&Ks[t][d4 * 4] = *(const float4*)(kp + d4 * 4);
            *(float4*)&Vs[t][d4 * 4] = *(const float4*)(kp + DD + d4 * 4);
        }
        __syncthreads();

        int jmax = (kt == qt) ? (t + 1) : 64;
        float tm = -3.0e38f;
        for (int j = 0; j < jmax; j++) {
            float s = 0.0f;
            #pragma unroll
            for (int d = 0; d < 64; d++) s += q[d] * Ks[j][d];
            Ss[j][t] = s;
            tm = fmaxf(tm, s);
        }
        float mnew = fmaxf(m, tm);
        float corr = __expf(m - mnew);
        l *= corr;
        #pragma unroll
        for (int d = 0; d < 64; d++) o[d] *= corr;
        for (int j = 0; j < jmax; j++) {
            float p = __expf(Ss[j][t] - mnew);
            l += p;
            #pragma unroll
            for (int d = 0; d < 64; d++) o[d] += p * Vs[j][d];
        }
        m = mnew;
        __syncthreads();
    }

    float inv = 1.0f / l;
    float* op = outp + ((size_t)(b * TT + qrow)) * DD + h * HDIM;
    #pragma unroll
    for (int d4 = 0; d4 < 16; d4++) {
        float4 v;
        v.x = o[d4 * 4 + 0] * inv;
        v.y = o[d4 * 4 + 1] * inv;
        v.z = o[d4 * 4 + 2] * inv;
        v.w = o[d4 * 4 + 3] * inv;
        *(float4*)(op + d4 * 4) = v;
    }
}

// ---------------------------------------------------------------------------
// Host launcher
// ---------------------------------------------------------------------------
extern "C" void kernel_launch(void* const* d_in, const int* in_sizes, int n_in,
                              void* d_out, int out_size)
{
    (void)in_sizes; (void)n_in; (void)out_size;
    const int*   ids    = (const int*)  d_in[0];
    const float* wte    = (const float*)d_in[1];
    const float* wpe    = (const float*)d_in[2];
    const float* ln1g   = (const float*)d_in[3];
    const float* ln1b   = (const float*)d_in[4];
    const float* wattn  = (const float*)d_in[5];
    const float* battn  = (const float*)d_in[6];
    const float* wproj  = (const float*)d_in[7];
    const float* bproj  = (const float*)d_in[8];
    const float* ln2g   = (const float*)d_in[9];
    const float* ln2b   = (const float*)d_in[10];
    const float* wfc    = (const float*)d_in[11];
    const float* bfc    = (const float*)d_in[12];
    const float* wmproj = (const float*)d_in[13];
    const float* bmproj = (const float*)d_in[14];
    const float* lnfg   = (const float*)d_in[15];
    const float* lnfb   = (const float*)d_in[16];
    float* out = (float*)d_out;

    float *px, *ph, *pqkv, *patt, *pfc;
    cudaGetSymbolAddress((void**)&px,   g_x);
    cudaGetSymbolAddress((void**)&ph,   g_h);
    cudaGetSymbolAddress((void**)&pqkv, g_qkv);
    cudaGetSymbolAddress((void**)&patt, g_att);
    cudaGetSymbolAddress((void**)&pfc,  g_fc);

    embed_kernel<<<MR, 192>>>(ids, wte, wpe, px);

    for (int l = 0; l < NL; l++) {
        ln_kernel<<<MR, 256>>>(px, ph, ln1g + (size_t)l * DD, ln1b + (size_t)l * DD);

        dim3 gqkv(MR / 128, (3 * DD) / 128);   // 32 x 18
        sgemm_kernel<EPI_BIAS, false><<<gqkv, 256>>>(
            ph, wattn + (size_t)l * DD * 3 * DD, battn + (size_t)l * 3 * DD,
            nullptr, pqkv, MR, 3 * DD, DD);

        dim3 gatt(TT / 64, NH, NB);            // 16 x 12 x 4
        attn_kernel<<<gatt, 64>>>(pqkv, patt);

        dim3 gproj(MR / 128, DD / 128);        // 32 x 6
        sgemm_kernel<EPI_BIAS_RES, false><<<gproj, 256>>>(
            patt, wproj + (size_t)l * DD * DD, bproj + (size_t)l * DD,
            px, px, MR, DD, DD);

        ln_kernel<<<MR, 256>>>(px, ph, ln2g + (size_t)l * DD, ln2b + (size_t)l * DD);

        dim3 gfc(MR / 128, (4 * DD) / 128);    // 32 x 24
        sgemm_kernel<EPI_BIAS_GELU, false><<<gfc, 256>>>(
            ph, wfc + (size_t)l * DD * 4 * DD, bfc + (size_t)l * 4 * DD,
            nullptr, pfc, MR, 4 * DD, DD);

        dim3 gmp(MR / 128, DD / 128);          // 32 x 6
        sgemm_kernel<EPI_BIAS_RES, false><<<gmp, 256>>>(
            pfc, wmproj + (size_t)l * 4 * DD * DD, bmproj + (size_t)l * DD,
            px, px, MR, DD, 4 * DD);
    }

    ln_kernel<<<MR, 256>>>(px, ph, lnfg, lnfb);

    dim3 glog(MR / 128, (VV + 127) / 128);     // 32 x 393, M fastest for wte L2 reuse
    sgemm_kernel<EPI_NONE, true><<<glog, 256>>>(
        ph, wte, nullptr, nullptr, out, MR, VV, DD);
}

// round 8
// speedup vs baseline: 1.6503x; 1.6503x over previous
#include <cuda_runtime.h>
#include <cuda_bf16.h>
#include <math.h>
#include <stdint.h>

#define TT 1024
#define DD 768
#define NH 12
#define NB 4
#define MR (NB*TT)
#define VV 50257
#define NL 12

// ------------------------- device scratch ----------------------------------
__device__ float g_x  [MR * DD];
__device__ float g_qkv[MR * 3 * DD];
__device__ __nv_bfloat16 g_hhi[MR*DD], g_hlo[MR*DD];
__device__ __nv_bfloat16 g_ahi[MR*DD], g_alo[MR*DD];
__device__ __nv_bfloat16 g_fhi[MR*4*DD], g_flo[MR*4*DD];
__device__ __nv_bfloat16 g_wq_h[NL*3*DD*DD], g_wq_l[NL*3*DD*DD];
__device__ __nv_bfloat16 g_wp_h[NL*DD*DD],   g_wp_l[NL*DD*DD];
__device__ __nv_bfloat16 g_wf_h[NL*4*DD*DD], g_wf_l[NL*4*DD*DD];
__device__ __nv_bfloat16 g_wm_h[NL*DD*4*DD], g_wm_l[NL*DD*4*DD];
__device__ __nv_bfloat16 g_wt_h[(size_t)VV*DD], g_wt_l[(size_t)VV*DD];

// ------------------------- helpers -----------------------------------------
__device__ __forceinline__ uint32_t smem_u32(const void* p){
    uint32_t a; asm("{ .reg .u64 t; cvta.to.shared.u64 t, %1; cvt.u32.u64 %0, t; }":"=r"(a):"l"(p)); return a;
}
__device__ __forceinline__ void cpasync16(uint32_t dst, const void* src, int srcsize){
    asm volatile("cp.async.cg.shared.global [%0], [%1], 16, %2;"
                 :: "r"(dst), "l"(src), "r"(srcsize) : "memory");
}
__device__ __forceinline__ void ldsm4(uint32_t& r0, uint32_t& r1, uint32_t& r2, uint32_t& r3, uint32_t a){
    asm volatile("ldmatrix.sync.aligned.m8n8.x4.shared.b16 {%0,%1,%2,%3}, [%4];"
                 : "=r"(r0),"=r"(r1),"=r"(r2),"=r"(r3) : "r"(a));
}
__device__ __forceinline__ void mma16816(float* d, const uint32_t* a, uint32_t b0, uint32_t b1){
    asm volatile("mma.sync.aligned.m16n8k16.row.col.f32.bf16.bf16.f32 "
                 "{%0,%1,%2,%3}, {%4,%5,%6,%7}, {%8,%9}, {%0,%1,%2,%3};"
                 : "+f"(d[0]),"+f"(d[1]),"+f"(d[2]),"+f"(d[3])
                 : "r"(a[0]),"r"(a[1]),"r"(a[2]),"r"(a[3]), "r"(b0),"r"(b1));
}
__device__ __forceinline__ float gelu_f(float x){
    const float c = 0.7978845608028654f;
    return 0.5f*x*(1.0f + tanhf(c*(x + 0.044715f*x*x*x)));
}
__device__ __forceinline__ void split_bf16(float v, __nv_bfloat16& hi, __nv_bfloat16& lo){
    hi = __float2bfloat16(v);
    lo = __float2bfloat16(v - __bfloat162float(hi));
}

// ---------------- weight conversion: [K,N] fp32 -> [N,K] bf16 hi/lo --------
__global__ void convt_kernel(const float* __restrict__ in, __nv_bfloat16* __restrict__ oh,
                             __nv_bfloat16* __restrict__ ol, int K, int N)
{
    __shared__ float tile[32][33];
    size_t zi = (size_t)blockIdx.z * K * N, zo = (size_t)blockIdx.z * N * K;
    int n0 = blockIdx.x*32, k0 = blockIdx.y*32, tx = threadIdx.x, ty = threadIdx.y;
    #pragma unroll
    for (int i = 0; i < 32; i += 8)
        tile[ty+i][tx] = in[zi + (size_t)(k0+ty+i)*N + n0+tx];
    __syncthreads();
    #pragma unroll
    for (int i = 0; i < 32; i += 8) {
        __nv_bfloat16 hi, lo; split_bf16(tile[tx][ty+i], hi, lo);
        size_t o = zo + (size_t)(n0+ty+i)*K + k0+tx;
        oh[o] = hi; ol[o] = lo;
    }
}
__global__ void conv_kernel(const float* __restrict__ in, __nv_bfloat16* __restrict__ oh,
                            __nv_bfloat16* __restrict__ ol, long cnt)
{
    long i = (long)blockIdx.x*blockDim.x + threadIdx.x;
    if (i < cnt) { __nv_bfloat16 h,l; split_bf16(in[i],h,l); oh[i]=h; ol[i]=l; }
}

// ------------------------------- embedding ---------------------------------
__global__ void embed_kernel(const int* __restrict__ ids, const float* __restrict__ wte,
                             const float* __restrict__ wpe, float* __restrict__ x)
{
    int r = blockIdx.x, tid = threadIdx.x;
    float4 a = *(const float4*)(wte + (size_t)ids[r]*DD + tid*4);
    float4 p = *(const float4*)(wpe + (size_t)(r&(TT-1))*DD + tid*4);
    float4 o; o.x=a.x+p.x; o.y=a.y+p.y; o.z=a.z+p.z; o.w=a.w+p.w;
    *(float4*)(x + (size_t)r*DD + tid*4) = o;
}

// ------------------------------- layernorm ---------------------------------
__global__ __launch_bounds__(256)
void ln_kernel(const float* __restrict__ in, __nv_bfloat16* __restrict__ oh,
               __nv_bfloat16* __restrict__ ol, const float* __restrict__ g,
               const float* __restrict__ b)
{
    __shared__ float red[8]; __shared__ float bc;
    int r = blockIdx.x, tid = threadIdx.x, lane = tid&31, wid = tid>>5;
    const float* row = in + (size_t)r*DD;
    float v0=row[tid], v1=row[tid+256], v2=row[tid+512];
    float s = v0+v1+v2;
    #pragma unroll
    for (int o=16;o>0;o>>=1) s += __shfl_xor_sync(~0u,s,o);
    if (lane==0) red[wid]=s;
    __syncthreads();
    if (tid==0){ float t=0; for(int i=0;i<8;i++) t+=red[i]; bc=t; }
    __syncthreads();
    float mu = bc*(1.f/768.f);
    float d0=v0-mu,d1=v1-mu,d2=v2-mu;
    float sq = d0*d0+d1*d1+d2*d2;
    #pragma unroll
    for (int o=16;o>0;o>>=1) sq += __shfl_xor_sync(~0u,sq,o);
    __syncthreads();
    if (lane==0) red[wid]=sq;
    __syncthreads();
    if (tid==0){ float t=0; for(int i=0;i<8;i++) t+=red[i]; bc=t; }
    __syncthreads();
    float rs = rsqrtf(bc*(1.f/768.f) + 1e-5f);
    size_t base = (size_t)r*DD;
    #pragma unroll
    for (int i=0;i<3;i++){
        int c = tid + i*256;
        float d = (i==0)?d0:(i==1)?d1:d2;
        __nv_bfloat16 hi,lo; split_bf16(d*rs*g[c]+b[c],hi,lo);
        oh[base+c]=hi; ol[base+c]=lo;
    }
}

// -------------- mma.sync GEMM: C[M,N] = A[M,K] @ B[N,K]^T ------------------
// bf16 hi/lo, 3 passes folded into chunk loop: AhBh, AlBh, AhBl. fp32 acc.
// EPI: 0 none->f32, 1 +bias->f32, 2 +bias,gelu->bf16 hi/lo, 3 +bias+res->f32
// 128x128 tile, BK=32, 8 warps (2x4), warp tile 64x32 (4x4 m16n8k16).
#define PAD 40          // bf16 per smem row (32 data + 8 pad), 80 B
#define STG (128*PAD)   // bf16 per stage

template<int EPI>
__global__ __launch_bounds__(256)
void mmagemm_kernel(const __nv_bfloat16* __restrict__ Ah, const __nv_bfloat16* __restrict__ Al,
                    const __nv_bfloat16* __restrict__ Bh, const __nv_bfloat16* __restrict__ Bl,
                    const float* __restrict__ bias, const float* __restrict__ res,
                    float* __restrict__ Cf, __nv_bfloat16* __restrict__ Chi,
                    __nv_bfloat16* __restrict__ Clo, int M, int N, int K)
{
    __shared__ __align__(16) __nv_bfloat16 sA[2*STG];
    __shared__ __align__(16) __nv_bfloat16 sB[2*STG];
    int tid = threadIdx.x, lane = tid&31, w = tid>>5;
    int wr = w>>2, wc = w&3;                 // warp row (0..1), warp col (0..3)
    int m0 = blockIdx.x*128, n0 = blockIdx.y*128;
    uint32_t smA = smem_u32(sA), smB = smem_u32(sB);

    float acc[4][4][4];
    #pragma unroll
    for (int i=0;i<4;i++) for (int j=0;j<4;j++) for (int k=0;k<4;k++) acc[i][j][k]=0.f;

    int ntk = K >> 5, nt3 = ntk*3;

    auto issue = [&](int c){
        int pass = c / ntk;
        int kk = (c - pass*ntk) << 5;
        int s = c & 1;
        const __nv_bfloat16* Ax = (pass==1) ? Al : Ah;
        const __nv_bfloat16* Bx = (pass==2) ? Bl : Bh;
        #pragma unroll
        for (int h = 0; h < 2; h++){
            int t = tid + h*256;             // 0..511
            int row = t>>2, seg = t&3;
            uint32_t da = smA + (uint32_t)(s*STG + row*PAD + seg*8)*2;
            cpasync16(da, Ax + (size_t)(m0+row)*K + kk + seg*8, 16);
            int n = n0 + row;
            uint32_t db = smB + (uint32_t)(s*STG + row*PAD + seg*8)*2;
            const __nv_bfloat16* bs = Bx + (size_t)(n < N ? n : 0)*K + kk + seg*8;
            cpasync16(db, bs, (n < N) ? 16 : 0);
        }
    };

    issue(0);
    asm volatile("cp.async.commit_group;" ::: "memory");

    for (int c = 0; c < nt3; c++){
        if (c+1 < nt3){
            issue(c+1);
            asm volatile("cp.async.commit_group;" ::: "memory");
            asm volatile("cp.async.wait_group 1;" ::: "memory");
        } else {
            asm volatile("cp.async.wait_group 0;" ::: "memory");
        }
        __syncthreads();

        int buf = c & 1;
        uint32_t aBase = smA + (uint32_t)(buf*STG)*2;
        uint32_t bBase = smB + (uint32_t)(buf*STG)*2;
        #pragma unroll
        for (int ks = 0; ks < 2; ks++){
            int colB = (ks*16 + ((lane>>4)<<3)) * 2;   // byte offset in row
            uint32_t af[4][4];
            #pragma unroll
            for (int mt = 0; mt < 4; mt++){
                int row = wr*64 + mt*16 + (lane&15);
                ldsm4(af[mt][0], af[mt][1], af[mt][2], af[mt][3],
                      aBase + (uint32_t)(row*PAD*2 + colB));
            }
            uint32_t bf[4][2];
            #pragma unroll
            for (int np = 0; np < 2; np++){
                int row = wc*32 + np*16 + (lane&15);
                uint32_t r0,r1,r2,r3;
                ldsm4(r0, r1, r2, r3, bBase + (uint32_t)(row*PAD*2 + colB));
                bf[np*2+0][0]=r0; bf[np*2+0][1]=r2;
                bf[np*2+1][0]=r1; bf[np*2+1][1]=r3;
            }
            #pragma unroll
            for (int mt = 0; mt < 4; mt++)
                #pragma unroll
                for (int nt = 0; nt < 4; nt++)
                    mma16816(acc[mt][nt], af[mt], bf[nt][0], bf[nt][1]);
        }
        __syncthreads();
    }

    // epilogue
    int tr = lane>>2, tc = (lane&3)*2;
    #pragma unroll
    for (int mt = 0; mt < 4; mt++){
        #pragma unroll
        for (int i = 0; i < 2; i++){
            int m = m0 + wr*64 + mt*16 + tr + i*8;
            #pragma unroll
            for (int nt = 0; nt < 4; nt++){
                #pragma unroll
                for (int j = 0; j < 2; j++){
                    int n = n0 + wc*32 + nt*8 + tc + j;
                    if (n < N){
                        float v = acc[mt][nt][i*2+j];
                        if (EPI != 0) v += bias[n];
                        size_t idx = (size_t)m*N + n;
                        if (EPI == 2){
                            __nv_bfloat16 hi,lo; split_bf16(gelu_f(v),hi,lo);
                            Chi[idx]=hi; Clo[idx]=lo;
                        } else if (EPI == 3){
                            Cf[idx] = v + res[idx];
                        } else {
                            Cf[idx] = v;
                        }
                    }
                }
            }
        }
    }
}

// ------------------------------- attention ---------------------------------
__global__ __launch_bounds__(128)
void attn_kernel(const float* __restrict__ qkv,
                 __nv_bfloat16* __restrict__ oh, __nv_bfloat16* __restrict__ ol)
{
    __shared__ float Ks[64][64];
    __shared__ float Vs[64][64];
    __shared__ float Ss[64][64];
    int qt = blockIdx.x, h = blockIdx.y, b = blockIdx.z;
    int t = threadIdx.x, row = t>>1, half = t&1;
    int qrow = qt*64 + row;
    unsigned pm = 3u << (t & 30);

    const float* qp = qkv + ((size_t)(b*TT + qrow))*(3*DD) + h*64 + half*32;
    float q[32];
    #pragma unroll
    for (int i = 0; i < 8; i++){
        float4 v = ((const float4*)qp)[i];
        q[4*i]=v.x*0.125f; q[4*i+1]=v.y*0.125f; q[4*i+2]=v.z*0.125f; q[4*i+3]=v.w*0.125f;
    }
    float o[32];
    #pragma unroll
    for (int d = 0; d < 32; d++) o[d] = 0.f;
    float m = -3.0e38f, l = 0.f;

    for (int kt = 0; kt <= qt; kt++){
        const float* kp = qkv + ((size_t)(b*TT + kt*64 + row))*(3*DD) + DD + h*64 + half*32;
        #pragma unroll
        for (int i = 0; i < 8; i++){
            ((float4*)&Ks[row][half*32])[i] = ((const float4*)kp)[i];
            ((float4*)&Vs[row][half*32])[i] = ((const float4*)(kp + DD))[i];
        }
        __syncthreads();

        int jmax = (kt==qt) ? (row+1) : 64;
        float tm = -3.0e38f;
        for (int j = 0; j < jmax; j++){
            const float* kr = &Ks[j][half*32];
            float s = 0.f;
            #pragma unroll
            for (int d = 0; d < 32; d++) s += q[d]*kr[d];
            s += __shfl_xor_sync(pm, s, 1);
            if (!half) Ss[j][row] = s;
            tm = fmaxf(tm, s);
        }
        __syncwarp();
        float mnew = fmaxf(m, tm);
        float corr = __expf(m - mnew);
        l *= corr;
        #pragma unroll
        for (int d = 0; d < 32; d++) o[d] *= corr;
        for (int j = 0; j < jmax; j++){
            float p = __expf(Ss[j][row] - mnew);
            l += p;
            const float* vr = &Vs[j][half*32];
            #pragma unroll
            for (int d = 0; d < 32; d++) o[d] += p*vr[d];
        }
        m = mnew;
        __syncthreads();
    }

    float inv = 1.f/l;
    size_t ob = ((size_t)(b*TT + qrow))*DD + h*64 + half*32;
    #pragma unroll
    for (int d = 0; d < 32; d++){
        __nv_bfloat16 hi,lo; split_bf16(o[d]*inv, hi, lo);
        oh[ob+d]=hi; ol[ob+d]=lo;
    }
}

// ------------------------------- launcher ----------------------------------
extern "C" void kernel_launch(void* const* d_in, const int* in_sizes, int n_in,
                              void* d_out, int out_size)
{
    (void)in_sizes; (void)n_in; (void)out_size;
    const int*   ids    = (const int*)  d_in[0];
    const float* wte    = (const float*)d_in[1];
    const float* wpe    = (const float*)d_in[2];
    const float* ln1g   = (const float*)d_in[3];
    const float* ln1b   = (const float*)d_in[4];
    const float* wattn  = (const float*)d_in[5];
    const float* battn  = (const float*)d_in[6];
    const float* wproj  = (const float*)d_in[7];
    const float* bproj  = (const float*)d_in[8];
    const float* ln2g   = (const float*)d_in[9];
    const float* ln2b   = (const float*)d_in[10];
    const float* wfc    = (const float*)d_in[11];
    const float* bfc    = (const float*)d_in[12];
    const float* wmproj = (const float*)d_in[13];
    const float* bmproj = (const float*)d_in[14];
    const float* lnfg   = (const float*)d_in[15];
    const float* lnfb   = (const float*)d_in[16];
    float* out = (float*)d_out;

    float *px, *pqkv;
    __nv_bfloat16 *phh,*phl,*pah,*pal,*pfh,*pfl;
    __nv_bfloat16 *wqh,*wql,*wph,*wpl,*wfh,*wfl,*wmh,*wml,*wth,*wtl;
    cudaGetSymbolAddress((void**)&px,   g_x);
    cudaGetSymbolAddress((void**)&pqkv, g_qkv);
    cudaGetSymbolAddress((void**)&phh,  g_hhi); cudaGetSymbolAddress((void**)&phl, g_hlo);
    cudaGetSymbolAddress((void**)&pah,  g_ahi); cudaGetSymbolAddress((void**)&pal, g_alo);
    cudaGetSymbolAddress((void**)&pfh,  g_fhi); cudaGetSymbolAddress((void**)&pfl, g_flo);
    cudaGetSymbolAddress((void**)&wqh,  g_wq_h); cudaGetSymbolAddress((void**)&wql, g_wq_l);
    cudaGetSymbolAddress((void**)&wph,  g_wp_h); cudaGetSymbolAddress((void**)&wpl, g_wp_l);
    cudaGetSymbolAddress((void**)&wfh,  g_wf_h); cudaGetSymbolAddress((void**)&wfl, g_wf_l);
    cudaGetSymbolAddress((void**)&wmh,  g_wm_h); cudaGetSymbolAddress((void**)&wml, g_wm_l);
    cudaGetSymbolAddress((void**)&wth,  g_wt_h); cudaGetSymbolAddress((void**)&wtl, g_wt_l);

    dim3 cb(32, 8);
    convt_kernel<<<dim3(3*DD/32, DD/32, NL),   cb>>>(wattn,  wqh, wql, DD,   3*DD);
    convt_kernel<<<dim3(DD/32,   DD/32, NL),   cb>>>(wproj,  wph, wpl, DD,   DD);
    convt_kernel<<<dim3(4*DD/32, DD/32, NL),   cb>>>(wfc,    wfh, wfl, DD,   4*DD);
    convt_kernel<<<dim3(DD/32, 4*DD/32, NL),   cb>>>(wmproj, wmh, wml, 4*DD, DD);
    long wcnt = (long)VV*DD;
    conv_kernel<<<(unsigned)((wcnt+255)/256), 256>>>(wte, wth, wtl, wcnt);

    embed_kernel<<<MR, 192>>>(ids, wte, wpe, px);

    for (int l = 0; l < NL; l++){
        ln_kernel<<<MR, 256>>>(px, phh, phl, ln1g + (size_t)l*DD, ln1b + (size_t)l*DD);

        mmagemm_kernel<1><<<dim3(MR/128, 3*DD/128), 256>>>(
            phh, phl, wqh + (size_t)l*3*DD*DD, wql + (size_t)l*3*DD*DD,
            battn + (size_t)l*3*DD, nullptr, pqkv, nullptr, nullptr, MR, 3*DD, DD);

        attn_kernel<<<dim3(TT/64, NH, NB), 128>>>(pqkv, pah, pal);

        mmagemm_kernel<3><<<dim3(MR/128, DD/128), 256>>>(
            pah, pal, wph + (size_t)l*DD*DD, wpl + (size_t)l*DD*DD,
            bproj + (size_t)l*DD, px, px, nullptr, nullptr, MR, DD, DD);

        ln_kernel<<<MR, 256>>>(px, phh, phl, ln2g + (size_t)l*DD, ln2b + (size_t)l*DD);

        mmagemm_kernel<2><<<dim3(MR/128, 4*DD/128), 256>>>(
            phh, phl, wfh + (size_t)l*4*DD*DD, wfl + (size_t)l*4*DD*DD,
            bfc + (size_t)l*4*DD, nullptr, nullptr, pfh, pfl, MR, 4*DD, DD);

        mmagemm_kernel<3><<<dim3(MR/128, DD/128), 256>>>(
            pfh, pfl, wmh + (size_t)l*DD*4*DD, wml + (size_t)l*DD*4*DD,
            bmproj + (size_t)l*DD, px, px, nullptr, nullptr, MR, DD, 4*DD);
    }

    ln_kernel<<<MR, 256>>>(px, phh, phl, lnfg, lnfb);

    mmagemm_kernel<0><<<dim3(MR/128, (VV+127)/128), 256>>>(
        phh, phl, wth, wtl, nullptr, nullptr, out, nullptr, nullptr, MR, VV, DD);
}

// round 9
// speedup vs baseline: 1.8160x; 1.1004x over previous
#include <cuda_runtime.h>
#include <cuda_bf16.h>
#include <math.h>
#include <stdint.h>

#define TT 1024
#define DD 768
#define NH 12
#define NB 4
#define MR (NB*TT)
#define VV 50257
#define NL 12

// ------------------------- device scratch ----------------------------------
__device__ float g_x  [MR * DD];
__device__ float g_qkv[MR * 3 * DD];
__device__ __nv_bfloat16 g_hhi[MR*DD], g_hlo[MR*DD];
__device__ __nv_bfloat16 g_ahi[MR*DD], g_alo[MR*DD];
__device__ __nv_bfloat16 g_fhi[MR*4*DD], g_flo[MR*4*DD];
__device__ __nv_bfloat16 g_wq_h[NL*3*DD*DD], g_wq_l[NL*3*DD*DD];
__device__ __nv_bfloat16 g_wp_h[NL*DD*DD],   g_wp_l[NL*DD*DD];
__device__ __nv_bfloat16 g_wf_h[NL*4*DD*DD], g_wf_l[NL*4*DD*DD];
__device__ __nv_bfloat16 g_wm_h[NL*DD*4*DD], g_wm_l[NL*DD*4*DD];
__device__ __nv_bfloat16 g_wt_h[(size_t)VV*DD], g_wt_l[(size_t)VV*DD];

// ------------------------- helpers -----------------------------------------
__device__ __forceinline__ uint32_t smem_u32(const void* p){
    uint32_t a; asm("{ .reg .u64 t; cvta.to.shared.u64 t, %1; cvt.u32.u64 %0, t; }":"=r"(a):"l"(p)); return a;
}
__device__ __forceinline__ void cpasync16(uint32_t dst, const void* src, int srcsize){
    asm volatile("cp.async.cg.shared.global [%0], [%1], 16, %2;"
                 :: "r"(dst), "l"(src), "r"(srcsize) : "memory");
}
__device__ __forceinline__ void ldsm4(uint32_t& r0, uint32_t& r1, uint32_t& r2, uint32_t& r3, uint32_t a){
    asm volatile("ldmatrix.sync.aligned.m8n8.x4.shared.b16 {%0,%1,%2,%3}, [%4];"
                 : "=r"(r0),"=r"(r1),"=r"(r2),"=r"(r3) : "r"(a));
}
__device__ __forceinline__ void mma16816(float* d, const uint32_t* a, uint32_t b0, uint32_t b1){
    asm volatile("mma.sync.aligned.m16n8k16.row.col.f32.bf16.bf16.f32 "
                 "{%0,%1,%2,%3}, {%4,%5,%6,%7}, {%8,%9}, {%0,%1,%2,%3};"
                 : "+f"(d[0]),"+f"(d[1]),"+f"(d[2]),"+f"(d[3])
                 : "r"(a[0]),"r"(a[1]),"r"(a[2]),"r"(a[3]), "r"(b0),"r"(b1));
}
__device__ __forceinline__ float gelu_f(float x){
    const float c = 0.7978845608028654f;
    return 0.5f*x*(1.0f + tanhf(c*(x + 0.044715f*x*x*x)));
}
__device__ __forceinline__ void split_bf16(float v, __nv_bfloat16& hi, __nv_bfloat16& lo){
    hi = __float2bfloat16(v);
    lo = __float2bfloat16(v - __bfloat162float(hi));
}

// ---------------- weight conversion: [K,N] fp32 -> [N,K] bf16 hi/lo --------
__global__ void convt_kernel(const float* __restrict__ in, __nv_bfloat16* __restrict__ oh,
                             __nv_bfloat16* __restrict__ ol, int K, int N)
{
    __shared__ float tile[32][33];
    size_t zi = (size_t)blockIdx.z * K * N, zo = (size_t)blockIdx.z * N * K;
    int n0 = blockIdx.x*32, k0 = blockIdx.y*32, tx = threadIdx.x, ty = threadIdx.y;
    #pragma unroll
    for (int i = 0; i < 32; i += 8)
        tile[ty+i][tx] = in[zi + (size_t)(k0+ty+i)*N + n0+tx];
    __syncthreads();
    #pragma unroll
    for (int i = 0; i < 32; i += 8) {
        __nv_bfloat16 hi, lo; split_bf16(tile[tx][ty+i], hi, lo);
        size_t o = zo + (size_t)(n0+ty+i)*K + k0+tx;
        oh[o] = hi; ol[o] = lo;
    }
}
__global__ void conv_kernel(const float* __restrict__ in, __nv_bfloat16* __restrict__ oh,
                            __nv_bfloat16* __restrict__ ol, long cnt)
{
    long i = (long)blockIdx.x*blockDim.x + threadIdx.x;
    if (i < cnt) { __nv_bfloat16 h,l; split_bf16(in[i],h,l); oh[i]=h; ol[i]=l; }
}

// ------------------------------- embedding ---------------------------------
__global__ void embed_kernel(const int* __restrict__ ids, const float* __restrict__ wte,
                             const float* __restrict__ wpe, float* __restrict__ x)
{
    int r = blockIdx.x, tid = threadIdx.x;
    float4 a = *(const float4*)(wte + (size_t)ids[r]*DD + tid*4);
    float4 p = *(const float4*)(wpe + (size_t)(r&(TT-1))*DD + tid*4);
    float4 o; o.x=a.x+p.x; o.y=a.y+p.y; o.z=a.z+p.z; o.w=a.w+p.w;
    *(float4*)(x + (size_t)r*DD + tid*4) = o;
}

// ------------------------------- layernorm ---------------------------------
__global__ __launch_bounds__(256)
void ln_kernel(const float* __restrict__ in, __nv_bfloat16* __restrict__ oh,
               __nv_bfloat16* __restrict__ ol, const float* __restrict__ g,
               const float* __restrict__ b)
{
    __shared__ float red[8]; __shared__ float bc;
    int r = blockIdx.x, tid = threadIdx.x, lane = tid&31, wid = tid>>5;
    const float* row = in + (size_t)r*DD;
    float v0=row[tid], v1=row[tid+256], v2=row[tid+512];
    float s = v0+v1+v2;
    #pragma unroll
    for (int o=16;o>0;o>>=1) s += __shfl_xor_sync(~0u,s,o);
    if (lane==0) red[wid]=s;
    __syncthreads();
    if (tid==0){ float t=0; for(int i=0;i<8;i++) t+=red[i]; bc=t; }
    __syncthreads();
    float mu = bc*(1.f/768.f);
    float d0=v0-mu,d1=v1-mu,d2=v2-mu;
    float sq = d0*d0+d1*d1+d2*d2;
    #pragma unroll
    for (int o=16;o>0;o>>=1) sq += __shfl_xor_sync(~0u,sq,o);
    __syncthreads();
    if (lane==0) red[wid]=sq;
    __syncthreads();
    if (tid==0){ float t=0; for(int i=0;i<8;i++) t+=red[i]; bc=t; }
    __syncthreads();
    float rs = rsqrtf(bc*(1.f/768.f) + 1e-5f);
    size_t base = (size_t)r*DD;
    #pragma unroll
    for (int i=0;i<3;i++){
        int c = tid + i*256;
        float d = (i==0)?d0:(i==1)?d1:d2;
        __nv_bfloat16 hi,lo; split_bf16(d*rs*g[c]+b[c],hi,lo);
        oh[base+c]=hi; ol[base+c]=lo;
    }
}

// -------------- mma.sync GEMM: C[M,N] = A[M,K] @ B[N,K]^T ------------------
// bf16 hi/lo, single K loop: per chunk load Ah/Al/Bh/Bl once, issue
// AhBh + AlBh + AhBl (drop AlBl, ~2^-18). fp32 acc.
// EPI: 0 none->f32, 1 +bias->f32, 2 +bias,gelu->bf16 hi/lo, 3 +bias+res->f32
// 128x128 tile, BK=32, 8 warps (2x4), warp tile 64x32 (4x4 m16n8k16).
#define PAD 40              // bf16 per smem row (32 data + 8 pad)
#define TSTG (128*PAD)      // bf16 per tile buffer
#define STAGE (4*TSTG)      // Ah, Al, Bh, Bl
#define GSM (2*STAGE*2)     // bytes: 2 stages  (163840... no: 2*4*10240 = 81920)

template<int EPI>
__global__ __launch_bounds__(256)
void mmagemm_kernel(const __nv_bfloat16* __restrict__ Ah, const __nv_bfloat16* __restrict__ Al,
                    const __nv_bfloat16* __restrict__ Bh, const __nv_bfloat16* __restrict__ Bl,
                    const float* __restrict__ bias, const float* __restrict__ res,
                    float* __restrict__ Cf, __nv_bfloat16* __restrict__ Chi,
                    __nv_bfloat16* __restrict__ Clo, int M, int N, int K)
{
    extern __shared__ __align__(16) __nv_bfloat16 sm[];
    int tid = threadIdx.x, lane = tid&31, w = tid>>5;
    int wr = w>>2, wc = w&3;
    int m0 = blockIdx.x*128, n0 = blockIdx.y*128;
    uint32_t smb = smem_u32(sm);

    float acc[4][4][4];
    #pragma unroll
    for (int i=0;i<4;i++) for (int j=0;j<4;j++) for (int k=0;k<4;k++) acc[i][j][k]=0.f;

    int ntk = K >> 5;

    auto issue = [&](int c){
        int kk = c << 5;
        uint32_t sb = smb + (uint32_t)((c&1)*STAGE)*2;
        #pragma unroll
        for (int h = 0; h < 2; h++){
            int t = tid + h*256;             // 0..511
            int row = t>>2, seg = t&3;
            uint32_t off = (uint32_t)(row*PAD + seg*8)*2;
            size_t ga = (size_t)(m0+row)*K + kk + seg*8;
            cpasync16(sb + off,             Ah + ga, 16);
            cpasync16(sb + TSTG*2 + off,    Al + ga, 16);
            int n = n0 + row;
            size_t gb = (size_t)(n < N ? n : 0)*K + kk + seg*8;
            int bsz = (n < N) ? 16 : 0;
            cpasync16(sb + 2*TSTG*2 + off,  Bh + gb, bsz);
            cpasync16(sb + 3*TSTG*2 + off,  Bl + gb, bsz);
        }
    };

    issue(0);
    asm volatile("cp.async.commit_group;" ::: "memory");

    for (int c = 0; c < ntk; c++){
        if (c+1 < ntk){
            issue(c+1);
            asm volatile("cp.async.commit_group;" ::: "memory");
            asm volatile("cp.async.wait_group 1;" ::: "memory");
        } else {
            asm volatile("cp.async.wait_group 0;" ::: "memory");
        }
        __syncthreads();

        uint32_t tb = smb + (uint32_t)((c&1)*STAGE)*2;
        #pragma unroll
        for (int ks = 0; ks < 2; ks++){
            uint32_t colB = (uint32_t)((ks*16 + ((lane>>4)<<3)) * 2);
            uint32_t ah[4][4], al[4][4];
            #pragma unroll
            for (int mt = 0; mt < 4; mt++){
                uint32_t ro = (uint32_t)((wr*64 + mt*16 + (lane&15))*PAD*2) + colB;
                ldsm4(ah[mt][0], ah[mt][1], ah[mt][2], ah[mt][3], tb + ro);
                ldsm4(al[mt][0], al[mt][1], al[mt][2], al[mt][3], tb + TSTG*2 + ro);
            }
            uint32_t bh[4][2], bl[4][2];
            #pragma unroll
            for (int np = 0; np < 2; np++){
                uint32_t ro = (uint32_t)((wc*32 + np*16 + (lane&15))*PAD*2) + colB;
                uint32_t r0,r1,r2,r3;
                ldsm4(r0, r1, r2, r3, tb + 2*TSTG*2 + ro);
                bh[np*2+0][0]=r0; bh[np*2+0][1]=r2;
                bh[np*2+1][0]=r1; bh[np*2+1][1]=r3;
                ldsm4(r0, r1, r2, r3, tb + 3*TSTG*2 + ro);
                bl[np*2+0][0]=r0; bl[np*2+0][1]=r2;
                bl[np*2+1][0]=r1; bl[np*2+1][1]=r3;
            }
            #pragma unroll
            for (int mt = 0; mt < 4; mt++)
                #pragma unroll
                for (int nt = 0; nt < 4; nt++){
                    mma16816(acc[mt][nt], ah[mt], bh[nt][0], bh[nt][1]);
                    mma16816(acc[mt][nt], al[mt], bh[nt][0], bh[nt][1]);
                    mma16816(acc[mt][nt], ah[mt], bl[nt][0], bl[nt][1]);
                }
        }
        __syncthreads();
    }

    // epilogue
    int tr = lane>>2, tc = (lane&3)*2;
    #pragma unroll
    for (int mt = 0; mt < 4; mt++){
        #pragma unroll
        for (int i = 0; i < 2; i++){
            int m = m0 + wr*64 + mt*16 + tr + i*8;
            #pragma unroll
            for (int nt = 0; nt < 4; nt++){
                #pragma unroll
                for (int j = 0; j < 2; j++){
                    int n = n0 + wc*32 + nt*8 + tc + j;
                    if (n < N){
                        float v = acc[mt][nt][i*2+j];
                        if (EPI != 0) v += bias[n];
                        size_t idx = (size_t)m*N + n;
                        if (EPI == 2){
                            __nv_bfloat16 hi,lo; split_bf16(gelu_f(v),hi,lo);
                            Chi[idx]=hi; Clo[idx]=lo;
                        } else if (EPI == 3){
                            Cf[idx] = v + res[idx];
                        } else {
                            Cf[idx] = v;
                        }
                    }
                }
            }
        }
    }
}

// ------------------------------- attention ---------------------------------
__global__ __launch_bounds__(128)
void attn_kernel(const float* __restrict__ qkv,
                 __nv_bfloat16* __restrict__ oh, __nv_bfloat16* __restrict__ ol)
{
    __shared__ float Ks[64][64];
    __shared__ float Vs[64][64];
    __shared__ float Ss[64][64];
    int qt = blockIdx.x, h = blockIdx.y, b = blockIdx.z;
    int t = threadIdx.x, row = t>>1, half = t&1;
    int qrow = qt*64 + row;
    unsigned pm = 3u << (t & 30);

    const float* qp = qkv + ((size_t)(b*TT + qrow))*(3*DD) + h*64 + half*32;
    float q[32];
    #pragma unroll
    for (int i = 0; i < 8; i++){
        float4 v = ((const float4*)qp)[i];
        q[4*i]=v.x*0.125f; q[4*i+1]=v.y*0.125f; q[4*i+2]=v.z*0.125f; q[4*i+3]=v.w*0.125f;
    }
    float o[32];
    #pragma unroll
    for (int d = 0; d < 32; d++) o[d] = 0.f;
    float m = -3.0e38f, l = 0.f;

    for (int kt = 0; kt <= qt; kt++){
        const float* kp = qkv + ((size_t)(b*TT + kt*64 + row))*(3*DD) + DD + h*64 + half*32;
        #pragma unroll
        for (int i = 0; i < 8; i++){
            ((float4*)&Ks[row][half*32])[i] = ((const float4*)kp)[i];
            ((float4*)&Vs[row][half*32])[i] = ((const float4*)(kp + DD))[i];
        }
        __syncthreads();

        int jmax = (kt==qt) ? (row+1) : 64;
        float tm = -3.0e38f;
        for (int j = 0; j < jmax; j++){
            const float* kr = &Ks[j][half*32];
            float s = 0.f;
            #pragma unroll
            for (int d = 0; d < 32; d++) s += q[d]*kr[d];
            s += __shfl_xor_sync(pm, s, 1);
            if (!half) Ss[j][row] = s;
            tm = fmaxf(tm, s);
        }
        __syncwarp();
        float mnew = fmaxf(m, tm);
        float corr = __expf(m - mnew);
        l *= corr;
        #pragma unroll
        for (int d = 0; d < 32; d++) o[d] *= corr;
        for (int j = 0; j < jmax; j++){
            float p = __expf(Ss[j][row] - mnew);
            l += p;
            const float* vr = &Vs[j][half*32];
            #pragma unroll
            for (int d = 0; d < 32; d++) o[d] += p*vr[d];
        }
        m = mnew;
        __syncthreads();
    }

    float inv = 1.f/l;
    size_t ob = ((size_t)(b*TT + qrow))*DD + h*64 + half*32;
    #pragma unroll
    for (int d = 0; d < 32; d++){
        __nv_bfloat16 hi,lo; split_bf16(o[d]*inv, hi, lo);
        oh[ob+d]=hi; ol[ob+d]=lo;
    }
}

// ------------------------------- launcher ----------------------------------
#define GSMEM_BYTES (2*STAGE*2)   // 81920

extern "C" void kernel_launch(void* const* d_in, const int* in_sizes, int n_in,
                              void* d_out, int out_size)
{
    (void)in_sizes; (void)n_in; (void)out_size;
    const int*   ids    = (const int*)  d_in[0];
    const float* wte    = (const float*)d_in[1];
    const float* wpe    = (const float*)d_in[2];
    const float* ln1g   = (const float*)d_in[3];
    const float* ln1b   = (const float*)d_in[4];
    const float* wattn  = (const float*)d_in[5];
    const float* battn  = (const float*)d_in[6];
    const float* wproj  = (const float*)d_in[7];
    const float* bproj  = (const float*)d_in[8];
    const float* ln2g   = (const float*)d_in[9];
    const float* ln2b   = (const float*)d_in[10];
    const float* wfc    = (const float*)d_in[11];
    const float* bfc    = (const float*)d_in[12];
    const float* wmproj = (const float*)d_in[13];
    const float* bmproj = (const float*)d_in[14];
    const float* lnfg   = (const float*)d_in[15];
    const float* lnfb   = (const float*)d_in[16];
    float* out = (float*)d_out;

    cudaFuncSetAttribute(mmagemm_kernel<0>, cudaFuncAttributeMaxDynamicSharedMemorySize, GSMEM_BYTES);
    cudaFuncSetAttribute(mmagemm_kernel<1>, cudaFuncAttributeMaxDynamicSharedMemorySize, GSMEM_BYTES);
    cudaFuncSetAttribute(mmagemm_kernel<2>, cudaFuncAttributeMaxDynamicSharedMemorySize, GSMEM_BYTES);
    cudaFuncSetAttribute(mmagemm_kernel<3>, cudaFuncAttributeMaxDynamicSharedMemorySize, GSMEM_BYTES);

    float *px, *pqkv;
    __nv_bfloat16 *phh,*phl,*pah,*pal,*pfh,*pfl;
    __nv_bfloat16 *wqh,*wql,*wph,*wpl,*wfh,*wfl,*wmh,*wml,*wth,*wtl;
    cudaGetSymbolAddress((void**)&px,   g_x);
    cudaGetSymbolAddress((void**)&pqkv, g_qkv);
    cudaGetSymbolAddress((void**)&phh,  g_hhi); cudaGetSymbolAddress((void**)&phl, g_hlo);
    cudaGetSymbolAddress((void**)&pah,  g_ahi); cudaGetSymbolAddress((void**)&pal, g_alo);
    cudaGetSymbolAddress((void**)&pfh,  g_fhi); cudaGetSymbolAddress((void**)&pfl, g_flo);
    cudaGetSymbolAddress((void**)&wqh,  g_wq_h); cudaGetSymbolAddress((void**)&wql, g_wq_l);
    cudaGetSymbolAddress((void**)&wph,  g_wp_h); cudaGetSymbolAddress((void**)&wpl, g_wp_l);
    cudaGetSymbolAddress((void**)&wfh,  g_wf_h); cudaGetSymbolAddress((void**)&wfl, g_wf_l);
    cudaGetSymbolAddress((void**)&wmh,  g_wm_h); cudaGetSymbolAddress((void**)&wml, g_wm_l);
    cudaGetSymbolAddress((void**)&wth,  g_wt_h); cudaGetSymbolAddress((void**)&wtl, g_wt_l);

    dim3 cb(32, 8);
    convt_kernel<<<dim3(3*DD/32, DD/32, NL),   cb>>>(wattn,  wqh, wql, DD,   3*DD);
    convt_kernel<<<dim3(DD/32,   DD/32, NL),   cb>>>(wproj,  wph, wpl, DD,   DD);
    convt_kernel<<<dim3(4*DD/32, DD/32, NL),   cb>>>(wfc,    wfh, wfl, DD,   4*DD);
    convt_kernel<<<dim3(DD/32, 4*DD/32, NL),   cb>>>(wmproj, wmh, wml, 4*DD, DD);
    long wcnt = (long)VV*DD;
    conv_kernel<<<(unsigned)((wcnt+255)/256), 256>>>(wte, wth, wtl, wcnt);

    embed_kernel<<<MR, 192>>>(ids, wte, wpe, px);

    for (int l = 0; l < NL; l++){
        ln_kernel<<<MR, 256>>>(px, phh, phl, ln1g + (size_t)l*DD, ln1b + (size_t)l*DD);

        mmagemm_kernel<1><<<dim3(MR/128, 3*DD/128), 256, GSMEM_BYTES>>>(
            phh, phl, wqh + (size_t)l*3*DD*DD, wql + (size_t)l*3*DD*DD,
            battn + (size_t)l*3*DD, nullptr, pqkv, nullptr, nullptr, MR, 3*DD, DD);

        attn_kernel<<<dim3(TT/64, NH, NB), 128>>>(pqkv, pah, pal);

        mmagemm_kernel<3><<<dim3(MR/128, DD/128), 256, GSMEM_BYTES>>>(
            pah, pal, wph + (size_t)l*DD*DD, wpl + (size_t)l*DD*DD,
            bproj + (size_t)l*DD, px, px, nullptr, nullptr, MR, DD, DD);

        ln_kernel<<<MR, 256>>>(px, phh, phl, ln2g + (size_t)l*DD, ln2b + (size_t)l*DD);

        mmagemm_kernel<2><<<dim3(MR/128, 4*DD/128), 256, GSMEM_BYTES>>>(
            phh, phl, wfh + (size_t)l*4*DD*DD, wfl + (size_t)l*4*DD*DD,
            bfc + (size_t)l*4*DD, nullptr, nullptr, pfh, pfl, MR, 4*DD, DD);

        mmagemm_kernel<3><<<dim3(MR/128, DD/128), 256, GSMEM_BYTES>>>(
            pfh, pfl, wmh + (size_t)l*DD*4*DD, wml + (size_t)l*DD*4*DD,
            bmproj + (size_t)l*DD, px, px, nullptr, nullptr, MR, DD, 4*DD);
    }

    ln_kernel<<<MR, 256>>>(px, phh, phl, lnfg, lnfb);

    mmagemm_kernel<0><<<dim3(MR/128, (VV+127)/128), 256, GSMEM_BYTES>>>(
        phh, phl, wth, wtl, nullptr, nullptr, out, nullptr, nullptr, MR, VV, DD);
}